// round 17
// baseline (speedup 1.0000x reference)
#include <cuda_runtime.h>
#include <cuda_fp16.h>
#include <math.h>
#include <stdint.h>

#define Nn 2048
#define Cc 1024
#define Hh 8
#define Dd 128
#define SCALE_F 25.0f
#define LOG2E 1.44269504088896f

typedef __half h16;

// ---------------- fp32 scratch ----------------
// pure scratch: [0,2)NnC attn@v partials; [4,6)NnC out partials.
__device__ __align__(128) float g_scratch[2 * Nn * 3 * Cc];
__device__ __align__(128) float g_S[(size_t)2 * Hh * Nn * Nn];   // base-2 logits
__device__ __align__(128) float g_simraw[Nn * Nn];
__device__ __align__(128) float g_attnsum[Nn * Nn];

// ---------------- fp16 operands ----------------
__device__ __align__(128) h16 g_xbP[2 * Nn * Cc];
__device__ __align__(128) h16 g_WqbB[2 * 3 * Cc * Cc];
__device__ __align__(128) h16 g_qkvh[2 * Nn * 3 * Cc];           // fp16 qkv, both sets
__device__ __align__(128) h16 g_qnP[2 * Hh * Nn * Dd];
__device__ __align__(128) h16 g_knB[2 * Hh * Nn * Dd];           // k * scale * log2e
__device__ __align__(128) h16 g_vT[Hh * Dd * Nn];
__device__ __align__(128) h16 g_vnB[Nn * Cc];
__device__ __align__(128) h16 g_attnP[(size_t)Hh * Nn * Nn];
__device__ __align__(128) h16 g_xP[Nn * 2 * Cc];                 // plain trans_cls
__device__ __align__(128) h16 g_sim2P[Nn * Nn];
__device__ __align__(128) h16 g_featB[2 * Cc * Nn];              // feat^T via W1 epilogue
__device__ __align__(128) h16 g_aveP[Nn * 4 * Cc];
__device__ __align__(128) h16 g_W1B[2 * Cc * 2 * Cc];
__device__ __align__(128) h16 g_W2B[Cc * 4 * Cc];

// ---------------- helpers ----------------
__device__ __forceinline__ float warpSum(float v) {
#pragma unroll
    for (int o = 16; o; o >>= 1) v += __shfl_xor_sync(0xffffffffu, v, o);
    return v;
}
__device__ float blockSum(float v, float* s) {
    int w = threadIdx.x >> 5, l = threadIdx.x & 31;
    v = warpSum(v);
    if (l == 0) s[w] = v;
    __syncthreads();
    float r = (l < 8) ? s[l] : 0.0f;
    r = warpSum(r);
    r = __shfl_sync(0xffffffffu, r, 0);
    __syncthreads();
    return r;
}
__device__ __forceinline__ uint32_t smem_u32(const void* p) {
    uint32_t a;
    asm("{ .reg .u64 t; cvta.to.shared.u64 t, %1; cvt.u32.u64 %0, t; }" : "=r"(a) : "l"(p));
    return a;
}
__device__ __forceinline__ void cp16(uint32_t s, const void* g) {
    asm volatile("cp.async.cg.shared.global [%0], [%1], 16;" :: "r"(s), "l"(g) : "memory");
}
__device__ __forceinline__ uint32_t swz(uint32_t off) {
    return off ^ ((off >> 3) & 0x70);
}
__device__ __forceinline__ void ldsm4(uint32_t* r, uint32_t a) {
    asm volatile("ldmatrix.sync.aligned.m8n8.x4.shared.b16 {%0,%1,%2,%3}, [%4];"
                 : "=r"(r[0]), "=r"(r[1]), "=r"(r[2]), "=r"(r[3]) : "r"(a));
}
__device__ __forceinline__ void mma16816(float* c, const uint32_t* a, uint32_t b0, uint32_t b1) {
    asm volatile(
        "mma.sync.aligned.m16n8k16.row.col.f32.f16.f16.f32 "
        "{%0,%1,%2,%3},{%4,%5,%6,%7},{%8,%9},{%0,%1,%2,%3};"
        : "+f"(c[0]), "+f"(c[1]), "+f"(c[2]), "+f"(c[3])
        : "r"(a[0]), "r"(a[1]), "r"(a[2]), "r"(a[3]), "r"(b0), "r"(b1));
}

// ---------------- HMMA GEMM: C[128x128] = A[M,K] * B[N,K]^T (+bias) ----------------
// z = z1 + nz1*z2:  A += z1*sA + z2*kofsA;  B += z1*sB + z2*kofsB;
//                   C += z1*sC + z2*sC2;    Ch += z1*sCh.
// Outputs (each optional): C fp32 (ldc); Ch plain fp16 (ldch); ChT transposed fp16 (ldchT).
#define STAGE_B 32768
#define GSMEM (2 * STAGE_B)

__global__ void __launch_bounds__(256, 2) gemm_mma(
    const h16* __restrict__ A, const h16* __restrict__ B,
    float* __restrict__ C, h16* __restrict__ Ch, h16* __restrict__ ChT,
    const float* __restrict__ bias, int K,
    long long lda, long long ldb, int ldc, int ldch, long long ldchT, int nz1,
    long long sA, long long sB, long long sC, long long sC2, long long sCh,
    long long kofsA, long long kofsB)
{
    extern __shared__ char smem[];
    const uint32_t sbase = smem_u32(smem);
    const int t = threadIdx.x, lane = t & 31, wid = t >> 5;
    const int wm = (wid & 3) * 32, wn = (wid >> 2) * 64;

    const int z1 = (int)(blockIdx.z % nz1);
    const int z2 = (int)(blockIdx.z / nz1);
    A += (long long)z1 * sA + (long long)z2 * kofsA;
    B += (long long)z1 * sB + (long long)z2 * kofsB;
    if (C)  C  += (long long)z1 * sC + (long long)z2 * sC2;
    if (Ch) Ch += (long long)z1 * sCh;
    const int m0 = blockIdx.y * 128, n0 = blockIdx.x * 128;

    const uint32_t aBuf[2] = {sbase,         sbase + STAGE_B};
    const uint32_t bBuf[2] = {sbase + 16384, sbase + STAGE_B + 16384};

    uint32_t ld_sw[4];
#pragma unroll
    for (int s = 0; s < 4; s++) {
        uint32_t off = (uint32_t)(t >> 1) * 128 + (uint32_t)(t & 1) * 64 + s * 16;
        ld_sw[s] = swz(off);
    }
    const h16* Ag = A + (long long)(m0 + (t >> 1)) * lda + (t & 1) * 32;
    const h16* Bg = B + (long long)(n0 + (t >> 1)) * ldb + (t & 1) * 32;

    auto LOAD = [&](int st, int ch) {
#pragma unroll
        for (int s = 0; s < 4; s++) {
            cp16(aBuf[st] + ld_sw[s], Ag + ch * 64 + s * 8);
            cp16(bBuf[st] + ld_sw[s], Bg + ch * 64 + s * 8);
        }
        asm volatile("cp.async.commit_group;" ::: "memory");
    };

    const uint32_t frow = (lane & 7) + ((lane >> 3) & 1) * 8;
    const uint32_t fbyte = (lane >> 4) * 16;

    float acc[2][8][4];
#pragma unroll
    for (int i = 0; i < 2; i++)
#pragma unroll
        for (int j = 0; j < 8; j++)
#pragma unroll
            for (int q = 0; q < 4; q++) acc[i][j][q] = 0.0f;

    const int nch = K >> 6;
    LOAD(0, 0);
    LOAD(1, 1);

    for (int c = 0; c < nch; ++c) {
        const int st = c & 1;
        asm volatile("cp.async.wait_group 1;" ::: "memory");
        __syncthreads();
#pragma unroll
        for (int ks = 0; ks < 4; ks++) {
            uint32_t bf[4][4], af[2][4];
#pragma unroll
            for (int jn = 0; jn < 4; jn++)
                ldsm4(bf[jn], bBuf[st] + swz((wn + jn * 16 + frow) * 128 + ks * 32 + fbyte));
#pragma unroll
            for (int i = 0; i < 2; i++)
                ldsm4(af[i], aBuf[st] + swz((wm + i * 16 + frow) * 128 + ks * 32 + fbyte));
#pragma unroll
            for (int i = 0; i < 2; i++)
#pragma unroll
                for (int j = 0; j < 8; j++) {
                    const int jn = j >> 1, sel = j & 1;
                    mma16816(acc[i][j], af[i], bf[jn][sel], bf[jn][sel + 2]);
                }
        }
        __syncthreads();
        if (c + 2 < nch) LOAD(st, c + 2);
    }

    // epilogue
    const int g = lane >> 2, tc = (lane & 3) * 2;
#pragma unroll
    for (int i = 0; i < 2; i++) {
        const int r0 = m0 + wm + i * 16 + g;
#pragma unroll
        for (int j = 0; j < 8; j++) {
            const int col = n0 + wn + j * 8 + tc;
            float bx = 0.0f, by = 0.0f;
            if (bias) { bx = bias[col]; by = bias[col + 1]; }
            float v00 = acc[i][j][0] + bx, v01 = acc[i][j][1] + by;
            float v10 = acc[i][j][2] + bx, v11 = acc[i][j][3] + by;
            if (C) {
                *(float2*)(C + (long long)r0 * ldc + col) = make_float2(v00, v01);
                *(float2*)(C + (long long)(r0 + 8) * ldc + col) = make_float2(v10, v11);
            }
            if (Ch) {
                *(__half2*)(Ch + (long long)r0 * ldch + col) =
                    __halves2half2(__float2half_rn(v00), __float2half_rn(v01));
                *(__half2*)(Ch + (long long)(r0 + 8) * ldch + col) =
                    __halves2half2(__float2half_rn(v10), __float2half_rn(v11));
            }
            if (ChT) {
                ChT[(long long)col * ldchT + r0]           = __float2half_rn(v00);
                ChT[(long long)(col + 1) * ldchT + r0]     = __float2half_rn(v01);
                ChT[(long long)col * ldchT + r0 + 8]       = __float2half_rn(v10);
                ChT[(long long)(col + 1) * ldchT + r0 + 8] = __float2half_rn(v11);
            }
        }
    }
}

// ---------------- converts ----------------
__global__ void cvtB_pair(const float* __restrict__ a, const float* __restrict__ b,
                          h16* __restrict__ dst, int K, long long R) {
    const size_t idx = ((size_t)blockIdx.x * blockDim.x + threadIdx.x) * 8;
    const size_t r = idx / K;
    const int j = (int)(idx % K);
    const float* src = ((long long)r < R) ? (a + r * K + j) : (b + (r - R) * K + j);
    float4 f0 = *(const float4*)src;
    float4 f1 = *(const float4*)(src + 4);
    __half2 hv[4];
    hv[0] = __halves2half2(__float2half_rn(f0.x), __float2half_rn(f0.y));
    hv[1] = __halves2half2(__float2half_rn(f0.z), __float2half_rn(f0.w));
    hv[2] = __halves2half2(__float2half_rn(f1.x), __float2half_rn(f1.y));
    hv[3] = __halves2half2(__float2half_rn(f1.z), __float2half_rn(f1.w));
    *(uint4*)(dst + idx) = *(uint4*)hv;
}
__global__ void cvtB1(const float* __restrict__ src, h16* __restrict__ dst) {
    const size_t idx = ((size_t)blockIdx.x * blockDim.x + threadIdx.x) * 8;
    float4 f0 = *(const float4*)(src + idx);
    float4 f1 = *(const float4*)(src + idx + 4);
    __half2 hv[4];
    hv[0] = __halves2half2(__float2half_rn(f0.x), __float2half_rn(f0.y));
    hv[1] = __halves2half2(__float2half_rn(f0.z), __float2half_rn(f0.w));
    hv[2] = __halves2half2(__float2half_rn(f1.x), __float2half_rn(f1.y));
    hv[3] = __halves2half2(__float2half_rn(f1.z), __float2half_rn(f1.w));
    *(uint4*)(dst + idx) = *(uint4*)hv;
}
// fp16 strided transpose: per z(head), qkvh v-slice [Nn x Dd] (lda 3C) -> vT[z] [Dd x Nn]
__global__ void cvtT_h(const h16* __restrict__ src, h16* __restrict__ dst) {
    src += 2 * Cc + (size_t)blockIdx.z * Dd;
    dst += (size_t)blockIdx.z * Dd * Nn;
    __shared__ h16 tile[32][33];
    const int c0 = blockIdx.x * 32, r0 = blockIdx.y * 32;
    const int tx = threadIdx.x, ty = threadIdx.y;
#pragma unroll
    for (int i = 0; i < 32; i += 8)
        tile[ty + i][tx] = src[(size_t)(r0 + ty + i) * 3 * Cc + c0 + tx];
    __syncthreads();
#pragma unroll
    for (int i = 0; i < 32; i += 8)
        dst[(size_t)(c0 + ty + i) * Nn + r0 + tx] = tile[tx][ty + i];
}

// split-K finalizers
__global__ void addcvt_x(const float* __restrict__ p0, const float* __restrict__ p1) {
    const size_t idx = ((size_t)blockIdx.x * blockDim.x + threadIdx.x) * 8;
    const size_t n = idx >> 10;
    const int c = (int)(idx & 1023);
    float4 a0 = *(const float4*)(p0 + idx), a1 = *(const float4*)(p0 + idx + 4);
    float4 b0 = *(const float4*)(p1 + idx), b1 = *(const float4*)(p1 + idx + 4);
    __half2 hv[4];
    hv[0] = __halves2half2(__float2half_rn(a0.x + b0.x), __float2half_rn(a0.y + b0.y));
    hv[1] = __halves2half2(__float2half_rn(a0.z + b0.z), __float2half_rn(a0.w + b0.w));
    hv[2] = __halves2half2(__float2half_rn(a1.x + b1.x), __float2half_rn(a1.y + b1.y));
    hv[3] = __halves2half2(__float2half_rn(a1.z + b1.z), __float2half_rn(a1.w + b1.w));
    *(uint4*)(g_xP + n * 2 * Cc + c) = *(uint4*)hv;
}
__global__ void add_bias_out(const float* __restrict__ p0, const float* __restrict__ p1,
                             const float* __restrict__ b2, float* __restrict__ out) {
    const size_t idx = ((size_t)blockIdx.x * blockDim.x + threadIdx.x) * 4;
    const int c = (int)(idx & 1023);
    float4 a = *(const float4*)(p0 + idx);
    float4 b = *(const float4*)(p1 + idx);
    float4 bb = *(const float4*)(b2 + c);
    float4 o = make_float4(a.x + b.x + bb.x, a.y + b.y + bb.y,
                           a.z + b.z + bb.z, a.w + b.w + bb.w);
    *(float4*)(out + idx) = o;
}

// ---------------- split + normalize + fold scales (reads fp16 qkv) ----------------
__global__ void split_normalize(const float* __restrict__ cls_score,
                                const float* __restrict__ fg_score) {
    const int n = blockIdx.x, h = blockIdx.y, j = threadIdx.x;
    const size_t setS = (size_t)Nn * 3 * Cc;
    const h16* bc = g_qkvh + (size_t)n * 3 * Cc + h * Dd + j;
    const h16* br = bc + setS;
    float qc = __half2float(bc[0]), kc = __half2float(bc[Cc]);
    h16 vh = bc[2 * Cc];
    float vv = __half2float(vh);
    float qr = __half2float(br[0]), kr = __half2float(br[Cc]);

    float sq[5] = {qc * qc, kc * kc, vv * vv, qr * qr, kr * kr};
    __shared__ float red[5][4];
    const int lane = j & 31, warp = j >> 5;
#pragma unroll
    for (int i = 0; i < 5; i++) {
        float v = warpSum(sq[i]);
        if (lane == 0) red[i][warp] = v;
    }
    __syncthreads();
    float inv[5];
#pragma unroll
    for (int i = 0; i < 5; i++)
        inv[i] = 1.0f / sqrtf(red[i][0] + red[i][1] + red[i][2] + red[i][3]);

    const float sc_c = SCALE_F * cls_score[n] * LOG2E;
    const float sc_f = SCALE_F * fg_score[n] * LOG2E;

    const size_t hb0 = ((size_t)h * Nn + n) * Dd + j;
    const size_t hb1 = ((size_t)(Hh + h) * Nn + n) * Dd + j;
    g_qnP[hb0] = __float2half_rn(qc * inv[0]);
    g_knB[hb0] = __float2half_rn(kc * inv[1] * sc_c);
    g_qnP[hb1] = __float2half_rn(qr * inv[3]);
    g_knB[hb1] = __float2half_rn(kr * inv[4] * sc_f);

    // x_ori -> xP cols [C .. 2C)
    g_xP[(size_t)n * 2 * Cc + Cc + h * Dd + j] = vh;

    g_vnB[(size_t)n * Cc + h * Dd + j] = __float2half_rn(vv * inv[2]);
}

// ---------------- dual softmax + combine + head-sum (register-resident, exp2) ----------------
__global__ void __launch_bounds__(256) softmax_combine() {
    const int n = blockIdx.x, t = threadIdx.x;
    __shared__ float red[8];
    const size_t set1 = (size_t)Hh * Nn * Nn;
    float acc[8];
#pragma unroll
    for (int i = 0; i < 8; i++) acc[i] = 0.0f;

    for (int h = 0; h < Hh; h++) {
        const size_t base = ((size_t)h * Nn + n) * Nn + t * 8;
        float a[8], b[8];
        *(float4*)&a[0] = *(const float4*)(g_S + base);
        *(float4*)&a[4] = *(const float4*)(g_S + base + 4);
        *(float4*)&b[0] = *(const float4*)(g_S + set1 + base);
        *(float4*)&b[4] = *(const float4*)(g_S + set1 + base + 4);
        float ec[8], er[8], lsc = 0.0f, lsr = 0.0f;
#pragma unroll
        for (int i = 0; i < 8; i++) {
            ec[i] = exp2f(a[i]); lsc += ec[i];
            er[i] = exp2f(b[i]); lsr += er[i];
        }
        const float ic = 0.5f / blockSum(lsc, red);
        const float ir = 0.5f / blockSum(lsr, red);
        __half2 hv[4];
#pragma unroll
        for (int q = 0; q < 4; q++) {
            float p0 = ec[2 * q] * ic + er[2 * q] * ir;
            float p1 = ec[2 * q + 1] * ic + er[2 * q + 1] * ir;
            acc[2 * q] += p0; acc[2 * q + 1] += p1;
            hv[q] = __halves2half2(__float2half_rn(p0), __float2half_rn(p1));
        }
        *(uint4*)(g_attnP + ((size_t)h * Nn + n) * Nn + t * 8) = *(uint4*)hv;
    }
    float* as = g_attnsum + (size_t)n * Nn + t * 8;
    *(float4*)as       = make_float4(acc[0], acc[1], acc[2], acc[3]);
    *(float4*)(as + 4) = make_float4(acc[4], acc[5], acc[6], acc[7]);
}

// ---------------- mask + softmax2 + renorm (register-resident, exp2) ----------------
__global__ void __launch_bounds__(256) mask_softmax2() {
    const int n = blockIdx.x, t = threadIdx.x;
    __shared__ float red[8];
    const size_t base = (size_t)n * Nn + t * 8;
    float v[8], sr[8];
    *(float4*)&v[0] = *(const float4*)(g_attnsum + base);
    *(float4*)&v[4] = *(const float4*)(g_attnsum + base + 4);
    *(float4*)&sr[0] = *(const float4*)(g_simraw + base);
    *(float4*)&sr[4] = *(const float4*)(g_simraw + base + 4);

    float e[8], ls = 0.0f;
#pragma unroll
    for (int i = 0; i < 8; i++) {
        e[i] = exp2f(v[i] * (0.125f * LOG2E));
        ls += e[i];
    }
    const float inv = 1.0f / blockSum(ls, red);
    float keep[8], lms = 0.0f;
#pragma unroll
    for (int i = 0; i < 8; i++) {
        keep[i] = (sr[i] > 6.0f) ? e[i] * inv : 0.0f;
        lms += keep[i];
    }
    const float invm = 1.0f / blockSum(lms, red);
    __half2 hv[4];
#pragma unroll
    for (int q = 0; q < 4; q++)
        hv[q] = __halves2half2(__float2half_rn(keep[2 * q] * invm),
                               __float2half_rn(keep[2 * q + 1] * invm));
    *(uint4*)(g_sim2P + base) = *(uint4*)hv;
}

// ---------------- launch ----------------
extern "C" void kernel_launch(void* const* d_in, const int* in_sizes, int n_in,
                              void* d_out, int out_size)
{
    const float* x_cls     = (const float*)d_in[0];
    const float* x_reg     = (const float*)d_in[1];
    const float* cls_score = (const float*)d_in[2];
    const float* fg_score  = (const float*)d_in[3];
    const float* W_qkv_cls = (const float*)d_in[4];
    const float* W_qkv_reg = (const float*)d_in[5];
    const float* W1        = (const float*)d_in[6];
    const float* b1        = (const float*)d_in[7];
    const float* W2        = (const float*)d_in[8];
    const float* b2        = (const float*)d_in[9];
    float* out = (float*)d_out;

    cudaFuncSetAttribute(gemm_mma, cudaFuncAttributeMaxDynamicSharedMemorySize, GSMEM);

#define ADDR(sym, var) float* var; cudaGetSymbolAddress((void**)&var, sym)
    ADDR(g_scratch, scratch); ADDR(g_S, S); ADDR(g_simraw, simraw);
#undef ADDR
#define HADDR(sym, var) h16* var; cudaGetSymbolAddress((void**)&var, sym)
    HADDR(g_xbP, xbP); HADDR(g_WqbB, WqbB); HADDR(g_qkvh, qkvh);
    HADDR(g_qnP, qnP); HADDR(g_knB, knB); HADDR(g_vT, vT);
    HADDR(g_vnB, vnB); HADDR(g_attnP, attnP);
    HADDR(g_xP, xP); HADDR(g_sim2P, sim2P); HADDR(g_featB, featB);
    HADDR(g_aveP, aveP); HADDR(g_W1B, W1B); HADDR(g_W2B, W2B);
#undef HADDR

    const long long NN  = (long long)Nn * Nn;
    const long long NnC = (long long)Nn * Cc;
    float* P0  = scratch;
    float* P1  = scratch + NnC;
    float* OP0 = scratch + 4 * NnC;
    float* OP1 = scratch + 5 * NnC;

    static cudaStream_t sA = nullptr, sB = nullptr;
    static cudaEvent_t eRoot, eWq, eSplit, eVt, eSoft, eMask, eWcvt, eW1, eOutB;
    if (sA == nullptr) {
        cudaStreamCreateWithFlags(&sA, cudaStreamNonBlocking);
        cudaStreamCreateWithFlags(&sB, cudaStreamNonBlocking);
        cudaEventCreateWithFlags(&eRoot,  cudaEventDisableTiming);
        cudaEventCreateWithFlags(&eWq,    cudaEventDisableTiming);
        cudaEventCreateWithFlags(&eSplit, cudaEventDisableTiming);
        cudaEventCreateWithFlags(&eVt,    cudaEventDisableTiming);
        cudaEventCreateWithFlags(&eSoft,  cudaEventDisableTiming);
        cudaEventCreateWithFlags(&eMask,  cudaEventDisableTiming);
        cudaEventCreateWithFlags(&eWcvt,  cudaEventDisableTiming);
        cudaEventCreateWithFlags(&eW1,    cudaEventDisableTiming);
        cudaEventCreateWithFlags(&eOutB,  cudaEventDisableTiming);
    }
    cudaStream_t s0 = 0;

    cudaEventRecord(eRoot, s0);
    cudaStreamWaitEvent(sA, eRoot, 0);
    cudaStreamWaitEvent(sB, eRoot, 0);

    // sA: Wq convert first (qkv GEMM waits eWq), then W1/W2 converts (eWcvt)
    cvtB_pair<<<(2 * 3 * Cc * Cc) / (256 * 8), 256, 0, sA>>>(W_qkv_cls, W_qkv_reg, WqbB, Cc, 3 * Cc);
    cudaEventRecord(eWq, sA);
    cvtB1<<<(2 * Cc * 2 * Cc) / (256 * 8), 256, 0, sA>>>(W1, W1B);
    cvtB1<<<(Cc * 4 * Cc) / (256 * 8), 256, 0, sA>>>(W2, W2B);
    cudaEventRecord(eWcvt, sA);

    // main: x convert -> qkv (fp16 out) -> split_normalize
    cvtB_pair<<<(2 * Nn * Cc) / (256 * 8), 256, 0, s0>>>(x_cls, x_reg, xbP, Cc, Nn);
    cudaStreamWaitEvent(s0, eWq, 0);
    gemm_mma<<<dim3(24, 16, 2), 256, GSMEM, s0>>>(
        xbP, WqbB, nullptr, qkvh, nullptr, nullptr, Cc,
        Cc, Cc, 0, 3 * Cc, 0, /*nz1=*/2,
        NnC, (long long)3 * Cc * Cc, 0, 0, (long long)Nn * 3 * Cc, 0, 0);
    split_normalize<<<dim3(Nn, Hh), 128, 0, s0>>>(cls_score, fg_score);
    cudaEventRecord(eSplit, s0);

    // sB: simraw + vT transpose (hidden under scores GEMM)
    cudaStreamWaitEvent(sB, eSplit, 0);
    gemm_mma<<<dim3(16, 16, 1), 256, GSMEM, sB>>>(
        vnB, vnB, simraw, nullptr, nullptr, nullptr, Cc,
        Cc, Cc, Nn, 0, 0, 1, 0, 0, 0, 0, 0, 0, 0);
    cvtT_h<<<dim3(4, 64, 8), dim3(32, 8), 0, sB>>>(qkvh, vT);
    cudaEventRecord(eVt, sB);

    // main: scores GEMM -> softmax_combine
    gemm_mma<<<dim3(16, 16, 16), 256, GSMEM, s0>>>(
        qnP, knB, S, nullptr, nullptr, nullptr, Dd,
        Dd, Dd, Nn, 0, 0, /*nz1=*/16,
        (long long)Nn * Dd, (long long)Nn * Dd, NN, 0, 0, 0, 0);
    softmax_combine<<<Nn, 256, 0, s0>>>();
    cudaEventRecord(eSoft, s0);

    // sB: mask_softmax2 (hidden under attn@v)
    cudaStreamWaitEvent(sB, eSoft, 0);
    mask_softmax2<<<Nn, 256, 0, sB>>>();
    cudaEventRecord(eMask, sB);

    // main: attn@v split-K=2 -> xP[:,0:C)
    cudaStreamWaitEvent(s0, eVt, 0);
    gemm_mma<<<dim3(1, 16, 16), 256, GSMEM, s0>>>(
        attnP, vT, P0, nullptr, nullptr, nullptr, /*K=*/Nn / 2,
        Nn, Nn, Cc, 0, 0, /*nz1=*/8,
        NN, (long long)Dd * Nn, (long long)Dd, NnC, 0,
        /*kofsA=*/Nn / 2, /*kofsB=*/Nn / 2);
    addcvt_x<<<(Nn * Cc) / (256 * 8), 256, 0, s0>>>(P0, P1);

    // main: W1 (K=2C, bias) -> aveP[:,2C:4C] + featB^T (join sA)
    cudaStreamWaitEvent(s0, eWcvt, 0);
    gemm_mma<<<dim3(16, 16, 1), 256, GSMEM, s0>>>(
        xP, W1B, nullptr, aveP + 2 * Cc, featB, b1, 2 * Cc,
        2 * Cc, 2 * Cc, 0, 4 * Cc, (long long)Nn, 1, 0, 0, 0, 0, 0, 0, 0);
    cudaEventRecord(eW1, s0);

    // sB: out feat-half (K = [2C,4C)) -> OP1, concurrent with sim2@feat
    cudaStreamWaitEvent(sB, eW1, 0);
    gemm_mma<<<dim3(8, 16, 1), 256, GSMEM, sB>>>(
        aveP + 2 * Cc, W2B + 2 * Cc, OP1, nullptr, nullptr, nullptr, 2 * Cc,
        4 * Cc, 4 * Cc, Cc, 0, 0, 1, 0, 0, 0, 0, 0, 0, 0);
    cudaEventRecord(eOutB, sB);

    // main: sim2@feat -> aveP[:,0:2C] (join sB via eMask)
    cudaStreamWaitEvent(s0, eMask, 0);
    gemm_mma<<<dim3(16, 16, 1), 256, GSMEM, s0>>>(
        sim2P, featB, nullptr, aveP, nullptr, nullptr, Nn,
        Nn, Nn, 0, 4 * Cc, 0, 1, 0, 0, 0, 0, 0, 0, 0);

    // main: out soft_sim-half (K = [0,2C)) -> OP0
    gemm_mma<<<dim3(8, 16, 1), 256, GSMEM, s0>>>(
        aveP, W2B, OP0, nullptr, nullptr, nullptr, 2 * Cc,
        4 * Cc, 4 * Cc, Cc, 0, 0, 1, 0, 0, 0, 0, 0, 0, 0);

    cudaStreamWaitEvent(s0, eOutB, 0);
    add_bias_out<<<(Nn * Cc) / (256 * 4), 256, 0, s0>>>(OP0, OP1, b2, out);
}